// round 12
// baseline (speedup 1.0000x reference)
#include <cuda_runtime.h>
#include <cuda_bf16.h>
#include <cstdint>
#include <math.h>

#define FIELD 39
#define EMBD 8
#define MAXB 16384
#define D0 312
#define D0P 320
#define D1 512
#define D2 256
#define D3 128

#define KW0 (D0P / 2)    // 160
#define KW1 (D1 / 2)     // 256
#define KW2 (D2 / 2)     // 128

// packed weights, layout [N][KW] (k-contiguous per output column)
__device__ unsigned g_w0p[D1 * KW0];
__device__ unsigned g_w1p[D2 * KW1];
__device__ unsigned g_w2p[D3 * KW2];

#define PACK_TOTAL (D1 * KW0 + D2 * KW1 + D3 * KW2)   // 163840

__device__ __forceinline__ unsigned pack_bf2(float a, float b) {
    __nv_bfloat162 p = __floats2bfloat162_rn(a, b);
    return *(unsigned*)&p;
}

// ---------------------------------------------------------------------------
// 1. weight pack kernel: out[n*KW + kp] = bf16x2(W[2kp][n], W[2kp+1][n])
// ---------------------------------------------------------------------------
__global__ __launch_bounds__(256) void pack_kernel(
    const float* __restrict__ W0, const float* __restrict__ W1,
    const float* __restrict__ W2)
{
    int p = blockIdx.x * 256 + threadIdx.x;
    if (p >= PACK_TOTAL) return;
    if (p < D1 * KW0) {
        int n = p / KW0, kp = p % KW0;
        int k = 2 * kp;
        float a = (k     < D0) ? W0[(size_t)k * D1 + n]       : 0.f;
        float c = (k + 1 < D0) ? W0[(size_t)(k + 1) * D1 + n] : 0.f;
        g_w0p[p] = pack_bf2(a, c);
    } else if (p < D1 * KW0 + D2 * KW1) {
        int q = p - D1 * KW0;
        int n = q / KW1, kp = q % KW1;
        int k = 2 * kp;
        g_w1p[q] = pack_bf2(W1[(size_t)k * D2 + n], W1[(size_t)(k + 1) * D2 + n]);
    } else {
        int q = p - D1 * KW0 - D2 * KW1;
        int n = q / KW2, kp = q % KW2;
        int k = 2 * kp;
        g_w2p[q] = pack_bf2(W2[(size_t)k * D3 + n], W2[(size_t)(k + 1) * D3 + n]);
    }
}

// ---------------------------------------------------------------------------
// fused MLP kernel: one CTA = 64 samples, whole network in smem.
// 512 threads = 16 warps (4x4), warp tile 16x32. B-side cp.async 3-stage.
// smem word offsets:
// ---------------------------------------------------------------------------
#define A0W 0          // 10 ktiles * 1024 words (40KB)
#define H1W 10240      // 16 ktiles (64KB)
#define H2W 26624      // 8 ktiles (32KB) ; early: Vi(2496w)+Ss(1521w)
#define BW  34816      // 3 stages * 2048 words (24KB)
#define LIVW 40960     // 64 words
#define REDW 41024     // 256 words
#define FUSED_SMEM ((REDW + 256) * 4)   // 165120 bytes

__device__ __forceinline__ void ldmx4(unsigned &r0, unsigned &r1, unsigned &r2,
                                      unsigned &r3, unsigned addr) {
    asm volatile("ldmatrix.sync.aligned.m8n8.x4.shared.b16 {%0,%1,%2,%3}, [%4];"
                 : "=r"(r0), "=r"(r1), "=r"(r2), "=r"(r3) : "r"(addr));
}

__device__ __forceinline__ void mma_bf16(float* c, const unsigned* a, const unsigned* b) {
    asm volatile(
        "mma.sync.aligned.m16n8k16.row.col.f32.bf16.bf16.f32 "
        "{%0,%1,%2,%3}, {%4,%5,%6,%7}, {%8,%9}, {%0,%1,%2,%3};"
        : "+f"(c[0]), "+f"(c[1]), "+f"(c[2]), "+f"(c[3])
        : "r"(a[0]), "r"(a[1]), "r"(a[2]), "r"(a[3]), "r"(b[0]), "r"(b[1]));
}

// B-stage loader: 512 threads, one 16B chunk each (stage = 128 n x 16 words)
__device__ __forceinline__ void load_B512(
    const unsigned* __restrict__ Wp, int KW, int bn, unsigned base,
    int t, int st, int kt)
{
    int n = t >> 2, c = t & 3;
    int pc = c ^ ((n >> 1) & 3);
    const unsigned* g = Wp + (size_t)(bn + n) * KW + kt * 16 + c * 4;
    unsigned s = base + (BW + st * 2048 + n * 16 + pc * 4) * 4;
    asm volatile("cp.async.cg.shared.global [%0], [%1], 16;" :: "r"(s), "l"(g));
}

// one k-tile compute for warp tile 16x32: acc[4][4]
__device__ __forceinline__ void tile16(
    unsigned aOff, unsigned bOff, int lane, int wm, int wn, float acc[4][4])
{
    const int lrow = lane & 15;
    const int lsel = lane >> 4;
#pragma unroll
    for (int s = 0; s < 2; s++) {
        int lc = 2 * s + lsel;
        unsigned b[4][2];
#pragma unroll
        for (int p = 0; p < 2; p++) {
            int n = wn + p * 16 + lrow;
            int pc = lc ^ ((n >> 1) & 3);
            unsigned r0, r1, r2, r3;
            ldmx4(r0, r1, r2, r3, bOff + (n * 16 + pc * 4) * 4);
            b[2 * p][0] = r0;  b[2 * p + 1][0] = r1;
            b[2 * p][1] = r2;  b[2 * p + 1][1] = r3;
        }
        int m = wm + lrow;
        int pc = lc ^ ((m >> 1) & 3);
        unsigned a[4];
        ldmx4(a[0], a[1], a[2], a[3], aOff + (m * 16 + pc * 4) * 4);
#pragma unroll
        for (int nt = 0; nt < 4; nt++)
            mma_bf16(acc[nt], a, b[nt]);
    }
}

__global__ __launch_bounds__(512, 1) void fused_mlp(
    const int* __restrict__ ids, const float* __restrict__ vals,
    const float* __restrict__ FM_W, const float* __restrict__ FM_V,
    const float* __restrict__ FM_B, const float* __restrict__ emb,
    const float* __restrict__ B0, const float* __restrict__ B1,
    const float* __restrict__ B2, const float* __restrict__ outW,
    const float* __restrict__ outB, float* __restrict__ out)
{
    extern __shared__ unsigned sm[];
    const unsigned base = (unsigned)__cvta_generic_to_shared(sm);
    const int t = threadIdx.x;
    const int lane = t & 31;
    const int warp = t >> 5;
    const int wm = (warp >> 2) * 16;   // 4 warp rows
    const int wn = (warp & 3) * 32;    // 4 warp cols
    const int bm = blockIdx.x * 64;

    // ---- 1. gather A0: 2560 16B chunks (10 ktiles x 64 rows x 4 chunks) ----
#pragma unroll
    for (int i = 0; i < 5; i++) {
        int id = t + 512 * i;
        int ktile = id >> 8, rr = id & 255;
        int m = rr >> 2, c = rr & 3;
        int f = ktile * 4 + c;
        unsigned w0 = 0u, w1 = 0u, w2 = 0u, w3 = 0u;
        if (f < FIELD) {
            int fid = ids[(bm + m) * FIELD + f];
            const float4* e = (const float4*)(emb + (size_t)fid * EMBD);
            float4 e0 = e[0];
            float4 e1 = e[1];
            w0 = pack_bf2(e0.x, e0.y);
            w1 = pack_bf2(e0.z, e0.w);
            w2 = pack_bf2(e1.x, e1.y);
            w3 = pack_bf2(e1.z, e1.w);
        }
        int pc = c ^ ((m >> 1) & 3);
        unsigned s = base + (A0W + ktile * 1024 + m * 16 + pc * 4) * 4;
        asm volatile("st.shared.v4.b32 [%0], {%1,%2,%3,%4};"
                     :: "r"(s), "r"(w0), "r"(w1), "r"(w2), "r"(w3));
    }

    // ---- 2. Vi/Ss in H2 region (free until layer-1 epilogue), then li ----
    float* Vi = (float*)(sm + H2W);             // 39*64 floats
    float* Ss = (float*)(sm + H2W + FIELD * 64);
    for (int idx = t; idx < FIELD * 64; idx += 512) {
        int i = idx / 64, r = idx % 64;
        long long off = (long long)i * (51000LL * 64LL) + r;
        Vi[idx] = FM_V[off];
    }
    __syncthreads();
    for (int idx = t; idx < FIELD * FIELD; idx += 512) {
        int i = idx / FIELD, j = idx % FIELD;
        float s = 0.f;
        if (j > i) {
#pragma unroll
            for (int e = 0; e < EMBD; e++)
                s += Vi[i * 64 + (j & 7) * 8 + e] * Vi[j * 64 + (i & 7) * 8 + e];
        }
        Ss[idx] = s;
    }
    __syncthreads();
    float* liv = (float*)(sm + LIVW);
    if (t < 64) {
        int b = bm + t;
        float v[FIELD];
        float lin = 0.f;
#pragma unroll
        for (int f = 0; f < FIELD; f++) {
            v[f] = vals[b * FIELD + f];
            lin += FM_W[ids[b * FIELD + f]] * v[f];
        }
        float inter = 0.f;
#pragma unroll
        for (int i = 0; i < FIELD; i++) {
            float ti = 0.f;
#pragma unroll
            for (int j = i + 1; j < FIELD; j++)
                ti += Ss[i * FIELD + j] * v[j];
            inter += v[i] * ti;
        }
        liv[t] = lin + inter + FM_B[0];
    }

    const unsigned* w0p = g_w0p;
    const unsigned* w1p = g_w1p;
    const unsigned* w2p = g_w2p;
    const int r = lane >> 2, cc = lane & 3;

    // ---- 3. layer 0: A0(smem) @ W0 -> h1(smem). nk=10, 4 n-tiles ----
#pragma unroll 1
    for (int nt4 = 0; nt4 < 4; nt4++) {
        int bn = nt4 * 128;
        float acc[4][4] = {};
        load_B512(w0p, KW0, bn, base, t, 0, 0);
        asm volatile("cp.async.commit_group;" ::: "memory");
        load_B512(w0p, KW0, bn, base, t, 1, 1);
        asm volatile("cp.async.commit_group;" ::: "memory");
#pragma unroll 1
        for (int kt = 0; kt < 10; kt++) {
            asm volatile("cp.async.wait_group 1;" ::: "memory");
            __syncthreads();
            if (kt + 2 < 10) load_B512(w0p, KW0, bn, base, t, (kt + 2) % 3, kt + 2);
            asm volatile("cp.async.commit_group;" ::: "memory");
            tile16(base + (A0W + kt * 1024) * 4,
                   base + (BW + (kt % 3) * 2048) * 4, lane, wm, wn, acc);
        }
        // epilogue -> h1 smem in A layout (kw = col/2 -> ktile/chunk/word)
#pragma unroll
        for (int nt = 0; nt < 4; nt++) {
            int col = bn + wn + nt * 8 + 2 * cc;
            float b0 = B0[col], b1 = B0[col + 1];
            int kw = col >> 1;
            int ktile = kw >> 4, kin = kw & 15, ch = kin >> 2, wi = kin & 3;
#pragma unroll
            for (int h = 0; h < 2; h++) {
                int row = wm + r + 8 * h;
                unsigned v = pack_bf2(fmaxf(acc[nt][2 * h] + b0, 0.f),
                                      fmaxf(acc[nt][2 * h + 1] + b1, 0.f));
                int pc2 = ch ^ ((row >> 1) & 3);
                sm[H1W + ktile * 1024 + row * 16 + pc2 * 4 + wi] = v;
            }
        }
        __syncthreads();
    }

    // ---- 4. layer 1: h1 @ W1 -> h2(smem). nk=16, 2 n-tiles ----
#pragma unroll 1
    for (int nt2 = 0; nt2 < 2; nt2++) {
        int bn = nt2 * 128;
        float acc[4][4] = {};
        load_B512(w1p, KW1, bn, base, t, 0, 0);
        asm volatile("cp.async.commit_group;" ::: "memory");
        load_B512(w1p, KW1, bn, base, t, 1, 1);
        asm volatile("cp.async.commit_group;" ::: "memory");
#pragma unroll 1
        for (int kt = 0; kt < 16; kt++) {
            asm volatile("cp.async.wait_group 1;" ::: "memory");
            __syncthreads();
            if (kt + 2 < 16) load_B512(w1p, KW1, bn, base, t, (kt + 2) % 3, kt + 2);
            asm volatile("cp.async.commit_group;" ::: "memory");
            tile16(base + (H1W + kt * 1024) * 4,
                   base + (BW + (kt % 3) * 2048) * 4, lane, wm, wn, acc);
        }
#pragma unroll
        for (int nt = 0; nt < 4; nt++) {
            int col = bn + wn + nt * 8 + 2 * cc;
            float b0 = B1[col], b1 = B1[col + 1];
            int kw = col >> 1;
            int ktile = kw >> 4, kin = kw & 15, ch = kin >> 2, wi = kin & 3;
#pragma unroll
            for (int h = 0; h < 2; h++) {
                int row = wm + r + 8 * h;
                unsigned v = pack_bf2(fmaxf(acc[nt][2 * h] + b0, 0.f),
                                      fmaxf(acc[nt][2 * h + 1] + b1, 0.f));
                int pc2 = ch ^ ((row >> 1) & 3);
                sm[H2W + ktile * 1024 + row * 16 + pc2 * 4 + wi] = v;
            }
        }
        __syncthreads();
    }

    // ---- 5. layer 2 + head: h2 @ W2, relu, dot outW, + li, sigmoid ----
    {
        float acc[4][4] = {};
        load_B512(w2p, KW2, 0, base, t, 0, 0);
        asm volatile("cp.async.commit_group;" ::: "memory");
        load_B512(w2p, KW2, 0, base, t, 1, 1);
        asm volatile("cp.async.commit_group;" ::: "memory");
#pragma unroll 1
        for (int kt = 0; kt < 8; kt++) {
            asm volatile("cp.async.wait_group 1;" ::: "memory");
            __syncthreads();
            if (kt + 2 < 8) load_B512(w2p, KW2, 0, base, t, (kt + 2) % 3, kt + 2);
            asm volatile("cp.async.commit_group;" ::: "memory");
            tile16(base + (H2W + kt * 1024) * 4,
                   base + (BW + (kt % 3) * 2048) * 4, lane, wm, wn, acc);
        }

        float p0 = 0.f, p1 = 0.f;
#pragma unroll
        for (int nt = 0; nt < 4; nt++) {
            int col = wn + nt * 8 + 2 * cc;
            float b0 = B2[col], b1 = B2[col + 1];
            float w0 = outW[col], w1 = outW[col + 1];
            p0 += fmaxf(acc[nt][0] + b0, 0.f) * w0
                + fmaxf(acc[nt][1] + b1, 0.f) * w1;
            p1 += fmaxf(acc[nt][2] + b0, 0.f) * w0
                + fmaxf(acc[nt][3] + b1, 0.f) * w1;
        }
        p0 += __shfl_xor_sync(0xffffffffu, p0, 1);
        p0 += __shfl_xor_sync(0xffffffffu, p0, 2);
        p1 += __shfl_xor_sync(0xffffffffu, p1, 1);
        p1 += __shfl_xor_sync(0xffffffffu, p1, 2);
        float* red = (float*)(sm + REDW);
        __syncthreads();   // red region: make sure nothing else in flight
        if (cc == 0) {
            red[(wm + r) * 4 + (warp & 3)] = p0;
            red[(wm + r + 8) * 4 + (warp & 3)] = p1;
        }
        __syncthreads();
        if (t < 64) {
            float s = red[t * 4] + red[t * 4 + 1] + red[t * 4 + 2] + red[t * 4 + 3];
            float x = s + outB[0] + liv[t];
            out[bm + t] = 1.f / (1.f + expf(-x));
        }
    }
}

// ---------------------------------------------------------------------------
extern "C" void kernel_launch(void* const* d_in, const int* in_sizes, int n_in,
                              void* d_out, int out_size)
{
    const int*   feat_ids  = (const int*)  d_in[0];
    const float* feat_vals = (const float*)d_in[1];
    const float* FM_W      = (const float*)d_in[2];
    const float* FM_V      = (const float*)d_in[3];
    const float* FM_B      = (const float*)d_in[4];
    const float* emb       = (const float*)d_in[5];
    const float* W0        = (const float*)d_in[6];
    const float* B0        = (const float*)d_in[7];
    const float* W1        = (const float*)d_in[8];
    const float* B1        = (const float*)d_in[9];
    const float* W2        = (const float*)d_in[10];
    const float* B2        = (const float*)d_in[11];
    const float* outW      = (const float*)d_in[12];
    const float* outB      = (const float*)d_in[13];
    float* out = (float*)d_out;

    int B = in_sizes[0] / FIELD;
    if (B > MAXB) B = MAXB;

    cudaFuncSetAttribute(fused_mlp,
                         cudaFuncAttributeMaxDynamicSharedMemorySize, FUSED_SMEM);

    pack_kernel<<<(PACK_TOTAL + 255) / 256, 256>>>(W0, W1, W2);

    fused_mlp<<<B / 64, 512, FUSED_SMEM>>>(feat_ids, feat_vals, FM_W, FM_V, FM_B,
                                           emb, B0, B1, B2, outW, outB, out);
}

// round 13
// speedup vs baseline: 1.0629x; 1.0629x over previous
#include <cuda_runtime.h>
#include <cuda_bf16.h>
#include <cstdint>
#include <math.h>

#define FIELD 39
#define EMBD 8
#define MAXB 16384
#define D0 312
#define D0P 320
#define D1 512
#define D2 256
#define D3 128

#define KW0 (D0P / 2)    // 160
#define KW1 (D1 / 2)     // 256
#define KW2 (D2 / 2)     // 128

// Scratch (allocation-free rule). Activations packed bf16x2, k-contiguous.
__device__ float    g_li[MAXB];
__device__ unsigned g_h0[MAXB * KW0];
__device__ unsigned g_h1[MAXB * KW1];
__device__ unsigned g_h2[MAXB * KW2];
// packed weights, layout [N][KW]
__device__ unsigned g_w0p[D1 * KW0];
__device__ unsigned g_w1p[D2 * KW1];
__device__ unsigned g_w2p[D3 * KW2];

__device__ __forceinline__ unsigned pack_bf2(float a, float b) {
    __nv_bfloat162 p = __floats2bfloat162_rn(a, b);
    return *(unsigned*)&p;
}

// ---------------------------------------------------------------------------
// 1. prep kernel: roles by block range:
//    [0,gB): gather -> g_h0 ; [gB,gB+liB): linear+inter (32 samples/block,
//    coalesced smem staging) ; [gB+liB, +160): weight pack via smem transpose
// ---------------------------------------------------------------------------
#define PACK_BLKS 160   // W0: 5x16=80, W1: 8x8=64, W2: 4x4=16

__global__ __launch_bounds__(256) void prep_kernel(
    const int* __restrict__ ids, const float* __restrict__ vals,
    const float* __restrict__ FM_W, const float* __restrict__ FM_V,
    const float* __restrict__ FM_B, const float* __restrict__ emb,
    const float* __restrict__ W0, const float* __restrict__ W1,
    const float* __restrict__ W2, int B, int gB, int liB)
{
    const int bid = blockIdx.x;
    const int t = threadIdx.x;

    if (bid < gB) {
        // ---- gather role: one (sample, field) per thread, pad f==39 ----
        int idx = bid * 256 + t;
        int b = idx / 40, f = idx % 40;
        uint4 o;
        if (f < FIELD) {
            int id = ids[b * FIELD + f];
            const float4* e = (const float4*)(emb + (size_t)id * EMBD);
            float4 e0 = e[0];
            float4 e1 = e[1];
            o.x = pack_bf2(e0.x, e0.y);
            o.y = pack_bf2(e0.z, e0.w);
            o.z = pack_bf2(e1.x, e1.y);
            o.w = pack_bf2(e1.z, e1.w);
        } else {
            o = make_uint4(0u, 0u, 0u, 0u);
        }
        *(uint4*)(g_h0 + (size_t)b * KW0 + f * 4) = o;
    } else if (bid < gB + liB) {
        // ---- li role: 32 samples per block ----
        __shared__ float Vi[FIELD * 64];
        __shared__ float Ss[FIELD * FIELD];
        __shared__ float vsm[32 * 40];
        __shared__ float lwsm[32 * 40];
        for (int idx = t; idx < FIELD * 64; idx += 256) {
            int i = idx / 64, r = idx % 64;
            long long off = (long long)i * (51000LL * 64LL) + r;
            Vi[idx] = FM_V[off];
        }
        __syncthreads();
        for (int idx = t; idx < FIELD * FIELD; idx += 256) {
            int i = idx / FIELD, j = idx % FIELD;
            float s = 0.f;
            if (j > i) {
#pragma unroll
                for (int e = 0; e < EMBD; e++)
                    s += Vi[i * 64 + (j & 7) * 8 + e] * Vi[j * 64 + (i & 7) * 8 + e];
            }
            Ss[idx] = s;
        }
        __syncthreads();

        // coalesced stage of 32*39 elements
        int sbase = (bid - gB) * 32;
        int ebase = sbase * FIELD;
        for (int e = t; e < 32 * FIELD; e += 256) {
            int s = e / FIELD, f = e % FIELD;
            int id = ids[ebase + e];
            float val = vals[ebase + e];
            vsm[s * 40 + f] = val;
            lwsm[s * 40 + f] = FM_W[id] * val;
        }
        __syncthreads();

        // 8 threads per sample
        int s = t >> 3, sub = t & 7;
        float p = 0.f;
        for (int f = sub; f < FIELD; f += 8) p += lwsm[s * 40 + f];
        for (int i = sub; i < FIELD; i += 8) {
            float ti = 0.f;
            for (int j = i + 1; j < FIELD; j++)
                ti += Ss[i * FIELD + j] * vsm[s * 40 + j];
            p += vsm[s * 40 + i] * ti;
        }
        p += __shfl_xor_sync(0xffffffffu, p, 1);
        p += __shfl_xor_sync(0xffffffffu, p, 2);
        p += __shfl_xor_sync(0xffffffffu, p, 4);
        if (sub == 0) g_li[sbase + s] = p + FM_B[0];
    } else {
        // ---- pack role: 32x32 (kp, n) tile with smem transpose ----
        __shared__ unsigned tile[32][33];
        int b2 = bid - gB - liB;
        const float* W; unsigned* G; int KW, N, K, kp0, n0;
        if (b2 < 80)       { W = W0; G = g_w0p; KW = KW0; N = D1; K = D0;
                             kp0 = (b2 % 5) * 32;  n0 = (b2 / 5) * 32; }
        else if (b2 < 144) { b2 -= 80; W = W1; G = g_w1p; KW = KW1; N = D2; K = D1;
                             kp0 = (b2 % 8) * 32;  n0 = (b2 / 8) * 32; }
        else               { b2 -= 144; W = W2; G = g_w2p; KW = KW2; N = D3; K = D2;
                             kp0 = (b2 % 4) * 32;  n0 = (b2 / 4) * 32; }
        int tx = t & 31, ty = t >> 5;
#pragma unroll
        for (int i = 0; i < 4; i++) {
            int kp = kp0 + ty * 4 + i;
            int k = 2 * kp;
            int n = n0 + tx;
            float a = (k     < K) ? W[(size_t)k * N + n]       : 0.f;
            float c = (k + 1 < K) ? W[(size_t)(k + 1) * N + n] : 0.f;
            tile[ty * 4 + i][tx] = pack_bf2(a, c);
        }
        __syncthreads();
#pragma unroll
        for (int i = 0; i < 4; i++) {
            int n = n0 + ty * 4 + i;
            int kp = kp0 + tx;
            G[(size_t)n * KW + kp] = tile[tx][ty * 4 + i];
        }
    }
}

// ---------------------------------------------------------------------------
// HMMA machinery (R7-proven), upgraded to 4-stage pipeline.
// BM=64, BN=128, BK=32 elems (16 words), 8 warps, warp tile 32x32.
// ---------------------------------------------------------------------------
#define SSTG 4
#define ASTG (64 * 16)    // 1024 words per A stage
#define BSTG (128 * 16)   // 2048 words per B stage
#define GSM_MID  ((SSTG * (ASTG + BSTG)) * 4)          // 49152
#define GSM_HEAD (GSM_MID + 256 * 4)                    // 50176

__device__ __forceinline__ void ldmx4(unsigned &r0, unsigned &r1, unsigned &r2,
                                      unsigned &r3, unsigned addr) {
    asm volatile("ldmatrix.sync.aligned.m8n8.x4.shared.b16 {%0,%1,%2,%3}, [%4];"
                 : "=r"(r0), "=r"(r1), "=r"(r2), "=r"(r3) : "r"(addr));
}

__device__ __forceinline__ void mma_bf16(float* c, const unsigned* a, const unsigned* b) {
    asm volatile(
        "mma.sync.aligned.m16n8k16.row.col.f32.bf16.bf16.f32 "
        "{%0,%1,%2,%3}, {%4,%5,%6,%7}, {%8,%9}, {%0,%1,%2,%3};"
        : "+f"(c[0]), "+f"(c[1]), "+f"(c[2]), "+f"(c[3])
        : "r"(a[0]), "r"(a[1]), "r"(a[2]), "r"(a[3]), "r"(b[0]), "r"(b[1]));
}

struct Frag { float acc[2][4][4]; };

__device__ __forceinline__ void tile_compute(
    unsigned aBase, unsigned bBase, int st, int lane, int wm, int wn, Frag &F)
{
    const int lrow = lane & 15;
    const int lsel = lane >> 4;
    unsigned aOff = aBase + st * ASTG * 4;
    unsigned bOff = bBase + st * BSTG * 4;
#pragma unroll
    for (int s = 0; s < 2; s++) {
        unsigned a[2][4], b[4][2];
        int lc = 2 * s + lsel;
#pragma unroll
        for (int p = 0; p < 2; p++) {
            int n = wn + p * 16 + lrow;
            int pc = lc ^ ((n >> 1) & 3);
            unsigned r0, r1, r2, r3;
            ldmx4(r0, r1, r2, r3, bOff + (n * 16 + pc * 4) * 4);
            b[2 * p][0] = r0;  b[2 * p + 1][0] = r1;
            b[2 * p][1] = r2;  b[2 * p + 1][1] = r3;
        }
#pragma unroll
        for (int mt = 0; mt < 2; mt++) {
            int m = wm + mt * 16 + lrow;
            int pc = lc ^ ((m >> 1) & 3);
            ldmx4(a[mt][0], a[mt][1], a[mt][2], a[mt][3],
                  aOff + (m * 16 + pc * 4) * 4);
        }
#pragma unroll
        for (int mt = 0; mt < 2; mt++)
#pragma unroll
            for (int nt = 0; nt < 4; nt++)
                mma_bf16(F.acc[mt][nt], a[mt], b[nt]);
    }
}

__device__ __forceinline__ void load_B(
    const unsigned* __restrict__ Wp, int KW, int bn, unsigned bBase,
    int t, int st, int kt)
{
    int kw0 = kt * 16;
#pragma unroll
    for (int i = 0; i < 2; i++) {
        int idx = t + 256 * i;
        int n = idx >> 2, c = idx & 3;
        int pc = c ^ ((n >> 1) & 3);
        const unsigned* g = Wp + (size_t)(bn + n) * KW + kw0 + c * 4;
        unsigned s = bBase + (st * BSTG + n * 16 + pc * 4) * 4;
        asm volatile("cp.async.cg.shared.global [%0], [%1], 16;" :: "r"(s), "l"(g));
    }
}

__device__ __forceinline__ void load_A(
    const unsigned* __restrict__ A, int KW, int bm, unsigned aBase,
    int t, int st, int kt)
{
    int m = t >> 2, c = t & 3;
    int pc = c ^ ((m >> 1) & 3);
    const unsigned* g = A + (size_t)(bm + m) * KW + kt * 16 + c * 4;
    unsigned s = aBase + (st * ASTG + m * 16 + pc * 4) * 4;
    asm volatile("cp.async.cg.shared.global [%0], [%1], 16;" :: "r"(s), "l"(g));
}

__device__ __forceinline__ void epilogue_pack(
    const float* __restrict__ bias, unsigned* __restrict__ C,
    int N, int bm, int bn, int lane, int wm, int wn, Frag &F)
{
    const int r = lane >> 2, cc = lane & 3;
    const int NW = N >> 1;
#pragma unroll
    for (int nt = 0; nt < 4; nt++) {
        int col = bn + wn + nt * 8 + 2 * cc;
        float b0 = bias[col], b1 = bias[col + 1];
        int cw = col >> 1;
#pragma unroll
        for (int mt = 0; mt < 2; mt++) {
            int row0 = bm + wm + mt * 16 + r;
            unsigned o0 = pack_bf2(fmaxf(F.acc[mt][nt][0] + b0, 0.f),
                                   fmaxf(F.acc[mt][nt][1] + b1, 0.f));
            unsigned o1 = pack_bf2(fmaxf(F.acc[mt][nt][2] + b0, 0.f),
                                   fmaxf(F.acc[mt][nt][3] + b1, 0.f));
            C[(size_t)row0 * NW + cw] = o0;
            C[(size_t)(row0 + 8) * NW + cw] = o1;
        }
    }
}

// ---------------------------------------------------------------------------
// 2. GEMM (layers 0 & 1): 4-stage pipeline, prefetch distance 3
// ---------------------------------------------------------------------------
__global__ __launch_bounds__(256, 3) void gemm_mid(
    const unsigned* __restrict__ A, const unsigned* __restrict__ Wp,
    const float* __restrict__ bias, unsigned* __restrict__ C,
    int N, int KW)
{
    extern __shared__ unsigned sm[];
    const int t = threadIdx.x;
    const int lane = t & 31;
    const int warp = t >> 5;
    const int wm = (warp >> 2) * 32;
    const int wn = (warp & 3) * 32;
    const int bm = blockIdx.y * 64;
    const int bn = blockIdx.x * 128;
    const unsigned aBase = (unsigned)__cvta_generic_to_shared(sm);
    const unsigned bBase = aBase + SSTG * ASTG * 4;
    const int nk = KW >> 4;

    Frag F = {};

#pragma unroll
    for (int s = 0; s < 3; s++) {
        load_A(A, KW, bm, aBase, t, s, s);
        load_B(Wp, KW, bn, bBase, t, s, s);
        asm volatile("cp.async.commit_group;" ::: "memory");
    }

    for (int kt = 0; kt < nk; kt++) {
        asm volatile("cp.async.wait_group 2;" ::: "memory");
        __syncthreads();

        int pf = kt + 3;
        if (pf < nk) {
            load_A(A, KW, bm, aBase, t, pf % SSTG, pf);
            load_B(Wp, KW, bn, bBase, t, pf % SSTG, pf);
        }
        asm volatile("cp.async.commit_group;" ::: "memory");

        tile_compute(aBase, bBase, kt % SSTG, lane, wm, wn, F);
    }

    epilogue_pack(bias, C, N, bm, bn, lane, wm, wn, F);
}

// ---------------------------------------------------------------------------
// 3. last GEMM fused with output head, 4-stage pipeline
// ---------------------------------------------------------------------------
__global__ __launch_bounds__(256, 3) void gemm_last_head(
    const unsigned* __restrict__ A, const unsigned* __restrict__ Wp,
    const float* __restrict__ bias, const float* __restrict__ outW,
    const float* __restrict__ outB, float* __restrict__ out, int KW)
{
    extern __shared__ unsigned sm[];
    const int t = threadIdx.x;
    const int lane = t & 31;
    const int warp = t >> 5;
    const int wm = (warp >> 2) * 32;
    const int wn = (warp & 3) * 32;
    const int bm = blockIdx.x * 64;
    const unsigned aBase = (unsigned)__cvta_generic_to_shared(sm);
    const unsigned bBase = aBase + SSTG * ASTG * 4;
    float* red = (float*)(sm + SSTG * (ASTG + BSTG));
    const int nk = KW >> 4;

    Frag F = {};

#pragma unroll
    for (int s = 0; s < 3; s++) {
        load_A(A, KW, bm, aBase, t, s, s);
        load_B(Wp, KW, 0, bBase, t, s, s);
        asm volatile("cp.async.commit_group;" ::: "memory");
    }

    for (int kt = 0; kt < nk; kt++) {
        asm volatile("cp.async.wait_group 2;" ::: "memory");
        __syncthreads();

        int pf = kt + 3;
        if (pf < nk) {
            load_A(A, KW, bm, aBase, t, pf % SSTG, pf);
            load_B(Wp, KW, 0, bBase, t, pf % SSTG, pf);
        }
        asm volatile("cp.async.commit_group;" ::: "memory");

        tile_compute(aBase, bBase, kt % SSTG, lane, wm, wn, F);
    }

    const int r = lane >> 2, cc = lane & 3;
#pragma unroll
    for (int mt = 0; mt < 2; mt++) {
        float p0 = 0.f, p1 = 0.f;
#pragma unroll
        for (int nt = 0; nt < 4; nt++) {
            int col = wn + nt * 8 + 2 * cc;
            float b0 = bias[col], b1 = bias[col + 1];
            float w0 = outW[col], w1 = outW[col + 1];
            p0 += fmaxf(F.acc[mt][nt][0] + b0, 0.f) * w0
                + fmaxf(F.acc[mt][nt][1] + b1, 0.f) * w1;
            p1 += fmaxf(F.acc[mt][nt][2] + b0, 0.f) * w0
                + fmaxf(F.acc[mt][nt][3] + b1, 0.f) * w1;
        }
        p0 += __shfl_xor_sync(0xffffffffu, p0, 1);
        p0 += __shfl_xor_sync(0xffffffffu, p0, 2);
        p1 += __shfl_xor_sync(0xffffffffu, p1, 1);
        p1 += __shfl_xor_sync(0xffffffffu, p1, 2);
        if (cc == 0) {
            red[(wm + mt * 16 + r) * 4 + (warp & 3)] = p0;
            red[(wm + mt * 16 + r + 8) * 4 + (warp & 3)] = p1;
        }
    }
    __syncthreads();
    if (t < 64) {
        float s = red[t * 4] + red[t * 4 + 1] + red[t * 4 + 2] + red[t * 4 + 3];
        float x = s + outB[0] + g_li[bm + t];
        out[bm + t] = 1.f / (1.f + expf(-x));
    }
}

// ---------------------------------------------------------------------------
extern "C" void kernel_launch(void* const* d_in, const int* in_sizes, int n_in,
                              void* d_out, int out_size)
{
    const int*   feat_ids  = (const int*)  d_in[0];
    const float* feat_vals = (const float*)d_in[1];
    const float* FM_W      = (const float*)d_in[2];
    const float* FM_V      = (const float*)d_in[3];
    const float* FM_B      = (const float*)d_in[4];
    const float* emb       = (const float*)d_in[5];
    const float* W0        = (const float*)d_in[6];
    const float* B0        = (const float*)d_in[7];
    const float* W1        = (const float*)d_in[8];
    const float* B1        = (const float*)d_in[9];
    const float* W2        = (const float*)d_in[10];
    const float* B2        = (const float*)d_in[11];
    const float* outW      = (const float*)d_in[12];
    const float* outB      = (const float*)d_in[13];
    float* out = (float*)d_out;

    int B = in_sizes[0] / FIELD;
    if (B > MAXB) B = MAXB;

    unsigned *h0, *h1, *h2, *w0p, *w1p, *w2p;
    cudaGetSymbolAddress((void**)&h0, g_h0);
    cudaGetSymbolAddress((void**)&h1, g_h1);
    cudaGetSymbolAddress((void**)&h2, g_h2);
    cudaGetSymbolAddress((void**)&w0p, g_w0p);
    cudaGetSymbolAddress((void**)&w1p, g_w1p);
    cudaGetSymbolAddress((void**)&w2p, g_w2p);

    cudaFuncSetAttribute(gemm_mid,
                         cudaFuncAttributeMaxDynamicSharedMemorySize, GSM_MID);
    cudaFuncSetAttribute(gemm_last_head,
                         cudaFuncAttributeMaxDynamicSharedMemorySize, GSM_HEAD);

    int gB = (B * 40 + 255) / 256;
    int liB = (B + 31) / 32;

    prep_kernel<<<gB + liB + PACK_BLKS, 256>>>(feat_ids, feat_vals, FM_W, FM_V,
                                               FM_B, emb, W0, W1, W2, B, gB, liB);

    gemm_mid<<<dim3(D1 / 128, B / 64), 256, GSM_MID>>>(h0, w0p, B0, h1, D1, KW0);
    gemm_mid<<<dim3(D2 / 128, B / 64), 256, GSM_MID>>>(h1, w1p, B1, h2, D2, KW1);
    gemm_last_head<<<B / 64, 256, GSM_HEAD>>>(h2, w2p, B2, outW, outB, out, KW2);
}